// round 2
// baseline (speedup 1.0000x reference)
#include <cuda_runtime.h>
#include <math.h>

#define N_NODES 100000
#define N_EDGES 1600000
#define CH 128
#define OUTC 64
#define NG 64

// ---------------- scratch (static device globals; no allocation) ----------------
__device__ __align__(16) float g_h[N_NODES * CH];   // GEMM output per layer
__device__ __align__(16) float g_x[N_NODES * CH];   // aggregated activation
__device__ float g_dinv[N_NODES];
__device__ int   g_counts[N_NODES];
__device__ int   g_rowstart[N_NODES + 1];
__device__ int   g_fill[N_NODES];
__device__ int   g_col[N_EDGES];
__device__ __align__(16) float g_pool[NG * CH];
__device__ float g_cnt[NG];

// ---------------- zero per-call state ----------------
__global__ void k_zero() {
    int i = blockIdx.x * blockDim.x + threadIdx.x;
    if (i < N_NODES) { g_counts[i] = 0; g_fill[i] = 0; }
    if (i < NG * CH) g_pool[i] = 0.f;
    if (i < NG)      g_cnt[i] = 0.f;
}

// ---------------- degree histogram ----------------
__global__ void k_count(const int* __restrict__ ei) {
    int e = blockIdx.x * blockDim.x + threadIdx.x;
    if (e < N_EDGES) {
        int d = ei[N_EDGES + e];
        atomicAdd(&g_counts[d], 1);
    }
}

// ---------------- single-block exclusive scan over counts -> rowstart ----------------
__global__ void k_scan() {
    __shared__ int sh[1024];
    int tid = threadIdx.x;
    int offset = 0;
    for (int base = 0; base < N_NODES; base += 1024) {
        int i = base + tid;
        int v = (i < N_NODES) ? g_counts[i] : 0;
        sh[tid] = v;
        __syncthreads();
        #pragma unroll
        for (int d = 1; d < 1024; d <<= 1) {
            int t2 = (tid >= d) ? sh[tid - d] : 0;
            __syncthreads();
            sh[tid] += t2;
            __syncthreads();
        }
        int incl = sh[tid];
        if (i < N_NODES) g_rowstart[i] = offset + incl - v;  // exclusive
        int total = sh[1023];
        offset += total;
        __syncthreads();
    }
    if (tid == 0) g_rowstart[N_NODES] = offset;
}

// ---------------- dinv = rsqrt(indeg + 1) ----------------
__global__ void k_dinv() {
    int i = blockIdx.x * blockDim.x + threadIdx.x;
    if (i < N_NODES) g_dinv[i] = rsqrtf((float)g_counts[i] + 1.0f);
}

// ---------------- CSR fill ----------------
__global__ void k_fill(const int* __restrict__ ei) {
    int e = blockIdx.x * blockDim.x + threadIdx.x;
    if (e < N_EDGES) {
        int s = ei[e];
        int d = ei[N_EDGES + e];
        int pos = g_rowstart[d] + atomicAdd(&g_fill[d], 1);
        g_col[pos] = s;
    }
}

// ---------------- fp32 GEMM: O[N,128] = X[N,128] @ W[128,128] + b ----------------
// Block tile: 64 rows x 128 cols, K-tiled by 16. 256 threads, each computes 4x8.
__global__ __launch_bounds__(256) void k_gemm(const float* __restrict__ X,
                                              const float* __restrict__ W,
                                              const float* __restrict__ B,
                                              float* __restrict__ O) {
    __shared__ float As[64][17];
    __shared__ __align__(16) float Bs[16][128];

    int t = threadIdx.x;
    int m0 = blockIdx.x * 64;
    int ty = t >> 4;   // 0..15 -> row group (4 rows)
    int tx = t & 15;   // 0..15 -> col group

    float acc[4][8];
    #pragma unroll
    for (int i = 0; i < 4; i++)
        #pragma unroll
        for (int j = 0; j < 8; j++) acc[i][j] = 0.f;

    int lrow = t >> 2;        // 0..63
    int lk   = (t & 3) * 4;   // 0,4,8,12
    int grow = m0 + lrow;
    bool rowok = (grow < N_NODES);

    for (int kb = 0; kb < 128; kb += 16) {
        float4 av = make_float4(0.f, 0.f, 0.f, 0.f);
        if (rowok) av = *(const float4*)(X + (size_t)grow * CH + kb + lk);
        As[lrow][lk + 0] = av.x; As[lrow][lk + 1] = av.y;
        As[lrow][lk + 2] = av.z; As[lrow][lk + 3] = av.w;

        int bk = t >> 5;          // 0..7
        int bc = (t & 31) * 4;    // 0..124
        float4 b0 = *(const float4*)(W + (kb + bk) * CH + bc);
        float4 b1 = *(const float4*)(W + (kb + bk + 8) * CH + bc);
        *(float4*)&Bs[bk][bc]     = b0;
        *(float4*)&Bs[bk + 8][bc] = b1;
        __syncthreads();

        #pragma unroll
        for (int k = 0; k < 16; k++) {
            float a0 = As[ty * 4 + 0][k];
            float a1 = As[ty * 4 + 1][k];
            float a2 = As[ty * 4 + 2][k];
            float a3 = As[ty * 4 + 3][k];
            float4 bl = *(float4*)&Bs[k][tx * 4];
            float4 bh = *(float4*)&Bs[k][64 + tx * 4];
            acc[0][0] += a0 * bl.x; acc[0][1] += a0 * bl.y; acc[0][2] += a0 * bl.z; acc[0][3] += a0 * bl.w;
            acc[0][4] += a0 * bh.x; acc[0][5] += a0 * bh.y; acc[0][6] += a0 * bh.z; acc[0][7] += a0 * bh.w;
            acc[1][0] += a1 * bl.x; acc[1][1] += a1 * bl.y; acc[1][2] += a1 * bl.z; acc[1][3] += a1 * bl.w;
            acc[1][4] += a1 * bh.x; acc[1][5] += a1 * bh.y; acc[1][6] += a1 * bh.z; acc[1][7] += a1 * bh.w;
            acc[2][0] += a2 * bl.x; acc[2][1] += a2 * bl.y; acc[2][2] += a2 * bl.z; acc[2][3] += a2 * bl.w;
            acc[2][4] += a2 * bh.x; acc[2][5] += a2 * bh.y; acc[2][6] += a2 * bh.z; acc[2][7] += a2 * bh.w;
            acc[3][0] += a3 * bl.x; acc[3][1] += a3 * bl.y; acc[3][2] += a3 * bl.z; acc[3][3] += a3 * bl.w;
            acc[3][4] += a3 * bh.x; acc[3][5] += a3 * bh.y; acc[3][6] += a3 * bh.z; acc[3][7] += a3 * bh.w;
        }
        __syncthreads();
    }

    float4 bias_l = *(const float4*)(B + tx * 4);
    float4 bias_h = *(const float4*)(B + 64 + tx * 4);
    #pragma unroll
    for (int i = 0; i < 4; i++) {
        int r = m0 + ty * 4 + i;
        if (r < N_NODES) {
            float4 ol = make_float4(acc[i][0] + bias_l.x, acc[i][1] + bias_l.y,
                                    acc[i][2] + bias_l.z, acc[i][3] + bias_l.w);
            float4 oh = make_float4(acc[i][4] + bias_h.x, acc[i][5] + bias_h.y,
                                    acc[i][6] + bias_h.z, acc[i][7] + bias_h.w);
            *(float4*)(O + (size_t)r * CH + tx * 4)      = ol;
            *(float4*)(O + (size_t)r * CH + 64 + tx * 4) = oh;
        }
    }
}

// ---------------- CSR gather aggregation ----------------
// O[n] = dinv[n]*(sum_s dinv[s]*H[s] + dinv[n]*H[n]); warp per node, float4 lanes.
__global__ __launch_bounds__(256) void k_agg(const float* __restrict__ H,
                                             float* __restrict__ O, int relu) {
    int node = blockIdx.x * 8 + (threadIdx.x >> 5);
    if (node >= N_NODES) return;
    int lane = threadIdx.x & 31;
    const float4* H4 = (const float4*)H;

    float dn = g_dinv[node];
    float4 hn = H4[node * 32 + lane];
    float4 acc = make_float4(dn * hn.x, dn * hn.y, dn * hn.z, dn * hn.w);

    int beg = g_rowstart[node];
    int end = g_rowstart[node + 1];
    #pragma unroll 4
    for (int e = beg; e < end; e++) {
        int s = g_col[e];
        float w = g_dinv[s];
        float4 hs = H4[s * 32 + lane];
        acc.x += w * hs.x;
        acc.y += w * hs.y;
        acc.z += w * hs.z;
        acc.w += w * hs.w;
    }
    acc.x *= dn; acc.y *= dn; acc.z *= dn; acc.w *= dn;
    if (relu) {
        acc.x = fmaxf(acc.x, 0.f); acc.y = fmaxf(acc.y, 0.f);
        acc.z = fmaxf(acc.z, 0.f); acc.w = fmaxf(acc.w, 0.f);
    }
    ((float4*)O)[node * 32 + lane] = acc;
}

// ---------------- mean-pool accumulation ----------------
__global__ __launch_bounds__(256) void k_pool(const float* __restrict__ H,
                                              const int* __restrict__ batch) {
    int node = blockIdx.x * 8 + (threadIdx.x >> 5);
    if (node >= N_NODES) return;
    int lane = threadIdx.x & 31;
    int g = batch[node];
    float4 v = ((const float4*)H)[node * 32 + lane];
    float* dst = &g_pool[g * CH + lane * 4];
    asm volatile("red.global.add.v4.f32 [%0], {%1,%2,%3,%4};"
                 :: "l"(dst), "f"(v.x), "f"(v.y), "f"(v.z), "f"(v.w) : "memory");
    if (lane == 0) atomicAdd(&g_cnt[g], 1.0f);
}

// ---------------- final projection: out[G,64] = (pool/cnt) @ Wp + bp ----------------
__global__ void k_final(const float* __restrict__ Wp, const float* __restrict__ bp,
                        float* __restrict__ out) {
    int g = blockIdx.x;      // 0..63
    int j = threadIdx.x;     // 0..63
    float inv = 1.0f / fmaxf(g_cnt[g], 1.0f);
    float acc = bp[j];
    #pragma unroll 4
    for (int c = 0; c < CH; c++)
        acc += g_pool[g * CH + c] * inv * Wp[c * OUTC + j];
    out[g * OUTC + j] = acc;
}

// ---------------- launch ----------------
extern "C" void kernel_launch(void* const* d_in, const int* in_sizes, int n_in,
                              void* d_out, int out_size) {
    const float* x   = (const float*)d_in[0];
    const int*   ei  = (const int*)d_in[1];     // int32 (JAX x64 disabled)
    const int*   bat = (const int*)d_in[2];     // int32
    const float* W1 = (const float*)d_in[3];
    const float* b1 = (const float*)d_in[4];
    const float* W2 = (const float*)d_in[5];
    const float* b2 = (const float*)d_in[6];
    const float* W3 = (const float*)d_in[7];
    const float* b3 = (const float*)d_in[8];
    const float* Wp = (const float*)d_in[9];
    const float* bp = (const float*)d_in[10];
    float* out = (float*)d_out;

    void *ph, *px;
    cudaGetSymbolAddress(&ph, g_h);
    cudaGetSymbolAddress(&px, g_x);
    float* hbuf = (float*)ph;
    float* xbuf = (float*)px;

    int nb_nodes = (N_NODES + 255) / 256;
    int nb_edges = (N_EDGES + 255) / 256;
    int nb_warp8 = (N_NODES + 7) / 8;
    int nb_gemm  = (N_NODES + 63) / 64;

    k_zero<<<nb_nodes, 256>>>();
    k_count<<<nb_edges, 256>>>(ei);
    k_scan<<<1, 1024>>>();
    k_dinv<<<nb_nodes, 256>>>();
    k_fill<<<nb_edges, 256>>>(ei);

    // layer 1
    k_gemm<<<nb_gemm, 256>>>(x, W1, b1, hbuf);
    k_agg<<<nb_warp8, 256>>>(hbuf, xbuf, 1);
    // layer 2
    k_gemm<<<nb_gemm, 256>>>(xbuf, W2, b2, hbuf);
    k_agg<<<nb_warp8, 256>>>(hbuf, xbuf, 1);
    // layer 3
    k_gemm<<<nb_gemm, 256>>>(xbuf, W3, b3, hbuf);
    k_agg<<<nb_warp8, 256>>>(hbuf, xbuf, 0);

    // pooling + projection
    k_pool<<<nb_warp8, 256>>>(xbuf, bat);
    k_final<<<NG, OUTC>>>(Wp, bp, out);
}

// round 4
// speedup vs baseline: 2.0572x; 2.0572x over previous
#include <cuda_runtime.h>
#include <cuda_bf16.h>
#include <math.h>
#include <stdint.h>

#define N_NODES 100000
#define N_EDGES 1600000
#define CH 128
#define OUTC 64
#define NG 64

// ---------------- scratch (static device globals; no allocation) ----------------
__device__ __align__(16) float g_h[N_NODES * CH];   // GEMM output per layer
__device__ __align__(16) float g_x[N_NODES * CH];   // aggregated activation
__device__ float g_dinv[N_NODES];
__device__ int   g_counts[N_NODES];
__device__ int   g_rowstart[N_NODES + 1];
__device__ int   g_fill[N_NODES];
__device__ int   g_col[N_EDGES];
__device__ int   g_bsum[256];
__device__ int   g_boff[256];
__device__ __align__(16) __nv_bfloat16 g_wh[CH * CH];  // W^T hi, [n][k]
__device__ __align__(16) __nv_bfloat16 g_wl[CH * CH];  // W^T lo, [n][k]
__device__ __align__(16) float g_pool[NG * CH];
__device__ float g_cnt[NG];

// ---------------- zero per-call state ----------------
__global__ void k_zero() {
    int i = blockIdx.x * blockDim.x + threadIdx.x;
    if (i < N_NODES) { g_counts[i] = 0; g_fill[i] = 0; }
    if (i < NG * CH) g_pool[i] = 0.f;
    if (i < NG)      g_cnt[i] = 0.f;
}

// ---------------- degree histogram ----------------
__global__ void k_count(const int* __restrict__ ei) {
    int e = blockIdx.x * blockDim.x + threadIdx.x;
    if (e < N_EDGES) atomicAdd(&g_counts[ei[N_EDGES + e]], 1);
}

// ---------------- multi-block scan pass 1 (block-local exclusive) ----------------
__global__ __launch_bounds__(512) void k_scan1() {
    __shared__ int sh[512];
    int i = blockIdx.x * 512 + threadIdx.x;
    int v = (i < N_NODES) ? g_counts[i] : 0;
    sh[threadIdx.x] = v;
    __syncthreads();
    #pragma unroll
    for (int d = 1; d < 512; d <<= 1) {
        int t = (threadIdx.x >= d) ? sh[threadIdx.x - d] : 0;
        __syncthreads();
        sh[threadIdx.x] += t;
        __syncthreads();
    }
    if (i < N_NODES) g_rowstart[i] = sh[threadIdx.x] - v;
    if (threadIdx.x == 511) g_bsum[blockIdx.x] = sh[511];
}

// ---------------- pass 2: scan block sums ----------------
__global__ __launch_bounds__(256) void k_scan2(int nblk) {
    __shared__ int sh[256];
    int t = threadIdx.x;
    int v = (t < nblk) ? g_bsum[t] : 0;
    sh[t] = v;
    __syncthreads();
    #pragma unroll
    for (int d = 1; d < 256; d <<= 1) {
        int tv = (t >= d) ? sh[t - d] : 0;
        __syncthreads();
        sh[t] += tv;
        __syncthreads();
    }
    g_boff[t] = sh[t] - v;
}

// ---------------- pass 3: add offsets; fused dinv ----------------
__global__ void k_scan3() {
    int i = blockIdx.x * blockDim.x + threadIdx.x;
    if (i < N_NODES) {
        g_rowstart[i] += g_boff[i >> 9];
        g_dinv[i] = rsqrtf((float)g_counts[i] + 1.0f);
    }
    if (i == 0) g_rowstart[N_NODES] = N_EDGES;
}

// ---------------- CSR fill ----------------
__global__ void k_fill(const int* __restrict__ ei) {
    int e = blockIdx.x * blockDim.x + threadIdx.x;
    if (e < N_EDGES) {
        int s = ei[e];
        int d = ei[N_EDGES + e];
        int pos = g_rowstart[d] + atomicAdd(&g_fill[d], 1);
        g_col[pos] = s;
    }
}

// ---------------- weight convert: W[k][n] fp32 -> W^T hi/lo bf16 [n][k] ----------------
__global__ void k_wconv(const float* __restrict__ W) {
    int i = blockIdx.x * blockDim.x + threadIdx.x;   // i = n*128 + k
    if (i < CH * CH) {
        int n = i >> 7, k = i & 127;
        float w = W[k * CH + n];
        __nv_bfloat16 h = __float2bfloat16(w);
        __nv_bfloat16 l = __float2bfloat16(w - __bfloat162float(h));
        g_wh[i] = h;
        g_wl[i] = l;
    }
}

// ---------------- mma.sync bf16 GEMM with hi/lo split ----------------
// O[N,128] = X[N,128] @ W[128,128] + b.  Block = 64 rows; 8 warps (2m x 4n), warp tile 32x32.
// smem rows padded to 136 bf16 (272B = 68 banks) -> conflict-free fragment LDS.
#define PAD 136
#define SM_AHI 0
#define SM_ALO (64 * PAD * 2)
#define SM_BHI (SM_ALO + 64 * PAD * 2)
#define SM_BLO (SM_BHI + 128 * PAD * 2)
#define SM_MMA_TOTAL (SM_BLO + 128 * PAD * 2)   // 104448 B

__device__ __forceinline__ void mma16816(float* c, const uint32_t* a, const uint32_t* b) {
    asm volatile("mma.sync.aligned.m16n8k16.row.col.f32.bf16.bf16.f32 "
                 "{%0,%1,%2,%3}, {%4,%5,%6,%7}, {%8,%9}, {%0,%1,%2,%3};"
                 : "+f"(c[0]), "+f"(c[1]), "+f"(c[2]), "+f"(c[3])
                 : "r"(a[0]), "r"(a[1]), "r"(a[2]), "r"(a[3]), "r"(b[0]), "r"(b[1]));
}
__device__ __forceinline__ uint32_t pack_bf2(float a, float b) {
    __nv_bfloat16 x = __float2bfloat16(a), y = __float2bfloat16(b);
    return (uint32_t)__bfloat16_as_ushort(x) | ((uint32_t)__bfloat16_as_ushort(y) << 16);
}

__global__ __launch_bounds__(256, 2) void k_gemm_mma(const float* __restrict__ X,
                                                     const float* __restrict__ B,
                                                     float* __restrict__ O) {
    extern __shared__ char smem[];
    int tid = threadIdx.x;
    int wid = tid >> 5;
    int lane = tid & 31;
    int m0 = blockIdx.x * 64;
    int m_w = (wid & 1) * 32;     // warp row offset within block
    int n_w = (wid >> 1) * 32;    // warp col offset

    // --- load + split X tile (64 x 128) into A_hi/A_lo ---
    for (int p = tid; p < 64 * 32; p += 256) {
        int row = p >> 5;
        int c4 = (p & 31) * 4;
        int gr = m0 + row;
        if (gr >= N_NODES) gr = 0;
        float4 v = *(const float4*)(X + (size_t)gr * CH + c4);
        float hx = __bfloat162float(__float2bfloat16(v.x));
        float hy = __bfloat162float(__float2bfloat16(v.y));
        float hz = __bfloat162float(__float2bfloat16(v.z));
        float hw = __bfloat162float(__float2bfloat16(v.w));
        uint32_t hp0 = pack_bf2(v.x, v.y), hp1 = pack_bf2(v.z, v.w);
        uint32_t lp0 = pack_bf2(v.x - hx, v.y - hy), lp1 = pack_bf2(v.z - hz, v.w - hw);
        char* ah = smem + SM_AHI + row * 272 + c4 * 2;
        char* al = smem + SM_ALO + row * 272 + c4 * 2;
        *(uint2*)ah = make_uint2(hp0, hp1);
        *(uint2*)al = make_uint2(lp0, lp1);
    }
    // --- load W^T hi/lo (128 x 128 bf16) into B_hi/B_lo ---
    for (int p = tid; p < 128 * 16; p += 256) {
        int n = p >> 4;
        int k8 = (p & 15) * 8;
        uint4 vh = *(const uint4*)(g_wh + n * CH + k8);
        uint4 vl = *(const uint4*)(g_wl + n * CH + k8);
        *(uint4*)(smem + SM_BHI + n * 272 + k8 * 2) = vh;
        *(uint4*)(smem + SM_BLO + n * 272 + k8 * 2) = vl;
    }
    __syncthreads();

    float acc[2][4][4];
    #pragma unroll
    for (int mt = 0; mt < 2; mt++)
        #pragma unroll
        for (int nt = 0; nt < 4; nt++)
            #pragma unroll
            for (int j = 0; j < 4; j++) acc[mt][nt][j] = 0.f;

    int q = lane >> 2;            // 0..7
    int km = (lane & 3) * 2;      // 0,2,4,6

    #pragma unroll
    for (int ks = 0; ks < 8; ks++) {
        int k0 = ks * 16;
        uint32_t ah[2][4], al[2][4], bh[4][2], bl[4][2];
        #pragma unroll
        for (int mt = 0; mt < 2; mt++) {
            int r = m_w + mt * 16 + q;
            const char* pa = smem + r * 272 + (k0 + km) * 2;
            ah[mt][0] = *(const uint32_t*)(pa + SM_AHI);
            ah[mt][1] = *(const uint32_t*)(pa + SM_AHI + 8 * 272);
            ah[mt][2] = *(const uint32_t*)(pa + SM_AHI + 16);
            ah[mt][3] = *(const uint32_t*)(pa + SM_AHI + 8 * 272 + 16);
            al[mt][0] = *(const uint32_t*)(pa + SM_ALO);
            al[mt][1] = *(const uint32_t*)(pa + SM_ALO + 8 * 272);
            al[mt][2] = *(const uint32_t*)(pa + SM_ALO + 16);
            al[mt][3] = *(const uint32_t*)(pa + SM_ALO + 8 * 272 + 16);
        }
        #pragma unroll
        for (int nt = 0; nt < 4; nt++) {
            int n = n_w + nt * 8 + q;
            const char* pb = smem + n * 272 + (k0 + km) * 2;
            bh[nt][0] = *(const uint32_t*)(pb + SM_BHI);
            bh[nt][1] = *(const uint32_t*)(pb + SM_BHI + 16);
            bl[nt][0] = *(const uint32_t*)(pb + SM_BLO);
            bl[nt][1] = *(const uint32_t*)(pb + SM_BLO + 16);
        }
        #pragma unroll
        for (int mt = 0; mt < 2; mt++)
            #pragma unroll
            for (int nt = 0; nt < 4; nt++) {
                mma16816(acc[mt][nt], ah[mt], bh[nt]);
                mma16816(acc[mt][nt], ah[mt], bl[nt]);
                mma16816(acc[mt][nt], al[mt], bh[nt]);
            }
    }

    // --- epilogue: bias + store ---
    #pragma unroll
    for (int nt = 0; nt < 4; nt++) {
        int c = n_w + nt * 8 + km;
        float bx = __ldg(B + c), by = __ldg(B + c + 1);
        #pragma unroll
        for (int mt = 0; mt < 2; mt++) {
            int r0 = m0 + m_w + mt * 16 + q;
            if (r0 < N_NODES)
                *(float2*)(O + (size_t)r0 * CH + c) =
                    make_float2(acc[mt][nt][0] + bx, acc[mt][nt][1] + by);
            int r1 = r0 + 8;
            if (r1 < N_NODES)
                *(float2*)(O + (size_t)r1 * CH + c) =
                    make_float2(acc[mt][nt][2] + bx, acc[mt][nt][3] + by);
        }
    }
}

// ---------------- CSR gather aggregation ----------------
__global__ __launch_bounds__(256) void k_agg(const float* __restrict__ H,
                                             float* __restrict__ O, int relu) {
    int node = blockIdx.x * 8 + (threadIdx.x >> 5);
    if (node >= N_NODES) return;
    int lane = threadIdx.x & 31;
    const float4* H4 = (const float4*)H;

    float dn = g_dinv[node];
    float4 hn = H4[node * 32 + lane];
    float4 acc = make_float4(dn * hn.x, dn * hn.y, dn * hn.z, dn * hn.w);

    int beg = g_rowstart[node];
    int end = g_rowstart[node + 1];
    #pragma unroll 4
    for (int e = beg; e < end; e++) {
        int s = g_col[e];
        float w = g_dinv[s];
        float4 hs = H4[s * 32 + lane];
        acc.x += w * hs.x;
        acc.y += w * hs.y;
        acc.z += w * hs.z;
        acc.w += w * hs.w;
    }
    acc.x *= dn; acc.y *= dn; acc.z *= dn; acc.w *= dn;
    if (relu) {
        acc.x = fmaxf(acc.x, 0.f); acc.y = fmaxf(acc.y, 0.f);
        acc.z = fmaxf(acc.z, 0.f); acc.w = fmaxf(acc.w, 0.f);
    }
    ((float4*)O)[node * 32 + lane] = acc;
}

// ---------------- mean-pool accumulation ----------------
__global__ __launch_bounds__(256) void k_pool(const float* __restrict__ H,
                                              const int* __restrict__ batch) {
    int node = blockIdx.x * 8 + (threadIdx.x >> 5);
    if (node >= N_NODES) return;
    int lane = threadIdx.x & 31;
    int g = batch[node];
    float4 v = ((const float4*)H)[node * 32 + lane];
    float* dst = &g_pool[g * CH + lane * 4];
    asm volatile("red.global.add.v4.f32 [%0], {%1,%2,%3,%4};"
                 :: "l"(dst), "f"(v.x), "f"(v.y), "f"(v.z), "f"(v.w) : "memory");
    if (lane == 0) atomicAdd(&g_cnt[g], 1.0f);
}

// ---------------- final projection ----------------
__global__ void k_final(const float* __restrict__ Wp, const float* __restrict__ bp,
                        float* __restrict__ out) {
    int g = blockIdx.x;
    int j = threadIdx.x;
    float inv = 1.0f / fmaxf(g_cnt[g], 1.0f);
    float acc = bp[j];
    #pragma unroll 4
    for (int c = 0; c < CH; c++)
        acc += g_pool[g * CH + c] * inv * Wp[c * OUTC + j];
    out[g * OUTC + j] = acc;
}

// ---------------- launch ----------------
extern "C" void kernel_launch(void* const* d_in, const int* in_sizes, int n_in,
                              void* d_out, int out_size) {
    const float* x   = (const float*)d_in[0];
    const int*   ei  = (const int*)d_in[1];
    const int*   bat = (const int*)d_in[2];
    const float* W1 = (const float*)d_in[3];
    const float* b1 = (const float*)d_in[4];
    const float* W2 = (const float*)d_in[5];
    const float* b2 = (const float*)d_in[6];
    const float* W3 = (const float*)d_in[7];
    const float* b3 = (const float*)d_in[8];
    const float* Wp = (const float*)d_in[9];
    const float* bp = (const float*)d_in[10];
    float* out = (float*)d_out;

    void *ph, *px;
    cudaGetSymbolAddress(&ph, g_h);
    cudaGetSymbolAddress(&px, g_x);
    float* hbuf = (float*)ph;
    float* xbuf = (float*)px;

    cudaFuncSetAttribute(k_gemm_mma, cudaFuncAttributeMaxDynamicSharedMemorySize, SM_MMA_TOTAL);

    int nb_nodes = (N_NODES + 255) / 256;
    int nb_edges = (N_EDGES + 255) / 256;
    int nb_warp8 = (N_NODES + 7) / 8;
    int nb_gemm  = (N_NODES + 63) / 64;
    int nb_scan1 = (N_NODES + 511) / 512;   // 196
    int nb_w     = (CH * CH + 255) / 256;

    k_zero<<<nb_nodes, 256>>>();
    k_count<<<nb_edges, 256>>>(ei);
    k_scan1<<<nb_scan1, 512>>>();
    k_scan2<<<1, 256>>>(nb_scan1);
    k_scan3<<<nb_nodes, 256>>>();
    k_fill<<<nb_edges, 256>>>(ei);

    // layer 1
    k_wconv<<<nb_w, 256>>>(W1);
    k_gemm_mma<<<nb_gemm, 256, SM_MMA_TOTAL>>>(x, b1, hbuf);
    k_agg<<<nb_warp8, 256>>>(hbuf, xbuf, 1);
    // layer 2
    k_wconv<<<nb_w, 256>>>(W2);
    k_gemm_mma<<<nb_gemm, 256, SM_MMA_TOTAL>>>(xbuf, b2, hbuf);
    k_agg<<<nb_warp8, 256>>>(hbuf, xbuf, 1);
    // layer 3
    k_wconv<<<nb_w, 256>>>(W3);
    k_gemm_mma<<<nb_gemm, 256, SM_MMA_TOTAL>>>(xbuf, b3, hbuf);
    k_agg<<<nb_warp8, 256>>>(hbuf, xbuf, 0);

    // pooling + projection
    k_pool<<<nb_warp8, 256>>>(xbuf, bat);
    k_final<<<NG, OUTC>>>(Wp, bp, out);
}